// round 6
// baseline (speedup 1.0000x reference)
#include <cuda_runtime.h>
#include <cuda_bf16.h>

#define Nn 100000
#define Ee 1600000
#define Dd 128
#define Hh 256
#define Ll 40
#define NB 98   // ceil(Nn / 1024)

// ---------------- scratch ------------------------------------------------------
__device__ int   g_degi[Nn];
__device__ int   g_offs[Nn + 1];
__device__ int   g_col[Ee];
__device__ int   g_part[NB];
__device__ int   g_base[NB];
__device__ float g_dinv[Nn];
__device__ float g_bufA[(size_t)Nn * Dd];
__device__ float g_bufB[(size_t)Nn * Dd];
__device__ float g_hid[(size_t)Nn * Hh];
// transposed bf16 hi/lo weights [N][K]:
//   W0,W1,W2: 128x128 ; Wm1: 256x128 ; Wm2: 64(pad from 40)x256
#define WT0 0
#define WT1 16384
#define WT2 32768
#define WTM1 49152
#define WTM2 81920
__device__ __nv_bfloat16 g_wtH[98304];
__device__ __nv_bfloat16 g_wtL[98304];

// ---------------- CSR build ----------------------------------------------------
__global__ void k_zero(int* __restrict__ a, int n) {
    int i = blockIdx.x * blockDim.x + threadIdx.x;
    if (i < n) a[i] = 0;
}

__global__ void k_bzero(__nv_bfloat16* __restrict__ a, __nv_bfloat16* __restrict__ b, int n) {
    int i = blockIdx.x * blockDim.x + threadIdx.x;
    if (i < n) { a[i] = __float2bfloat16(0.f); b[i] = __float2bfloat16(0.f); }
}

__global__ void k_count(const int* __restrict__ ei, int* __restrict__ degi, int e) {
    int i = blockIdx.x * blockDim.x + threadIdx.x;
    if (i < e) atomicAdd(&degi[ei[i]], 1);
}

__global__ void k_dinv(const int* __restrict__ degi, float* __restrict__ dinv, int n) {
    int i = blockIdx.x * blockDim.x + threadIdx.x;
    if (i < n) dinv[i] = rsqrtf((float)degi[i] + 1.0f);
}

__global__ void k_scanA(const int* __restrict__ degi, int* __restrict__ part) {
    __shared__ int s[1024];
    int i = blockIdx.x * 1024 + threadIdx.x;
    s[threadIdx.x] = (i < Nn) ? degi[i] : 0;
    __syncthreads();
    for (int d = 512; d > 0; d >>= 1) {
        if (threadIdx.x < d) s[threadIdx.x] += s[threadIdx.x + d];
        __syncthreads();
    }
    if (threadIdx.x == 0) part[blockIdx.x] = s[0];
}

__global__ void k_scanB(const int* __restrict__ part, int* __restrict__ base) {
    __shared__ int s[128];
    int t = threadIdx.x;
    int v = (t < NB) ? part[t] : 0;
    s[t] = v;
    __syncthreads();
    for (int d = 1; d < 128; d <<= 1) {
        int u = (t >= d) ? s[t - d] : 0;
        __syncthreads();
        s[t] += u;
        __syncthreads();
    }
    if (t < NB) base[t] = s[t] - v;
}

__global__ void k_scanC(const int* __restrict__ degi, const int* __restrict__ base,
                        int* __restrict__ offs) {
    __shared__ int s[1024];
    int t = threadIdx.x;
    int i = blockIdx.x * 1024 + t;
    int v = (i < Nn) ? degi[i] : 0;
    s[t] = v;
    __syncthreads();
    for (int d = 1; d < 1024; d <<= 1) {
        int u = (t >= d) ? s[t - d] : 0;
        __syncthreads();
        s[t] += u;
        __syncthreads();
    }
    int exc = s[t] - v + base[blockIdx.x];
    if (i < Nn) {
        offs[i] = exc;
        if (i == Nn - 1) offs[Nn] = exc + v;
    }
}

__global__ void k_fill(const int* __restrict__ ei, const int* __restrict__ offs,
                       int* __restrict__ degi, int* __restrict__ col, int e) {
    int i = blockIdx.x * blockDim.x + threadIdx.x;
    if (i < e) {
        int r = ei[i];
        int c = ei[e + i];
        int pos = offs[r] + atomicSub(&degi[r], 1) - 1;
        col[pos] = c;
    }
}

// ---------------- weight conversion: W[K][N] -> Wt hi/lo [N][K] ---------------
__global__ void k_wconv(const float* __restrict__ W, __nv_bfloat16* __restrict__ H,
                        __nv_bfloat16* __restrict__ L, int K, int N) {
    int i = blockIdx.x * blockDim.x + threadIdx.x;
    if (i < K * N) {
        int k = i / N, n = i % N;
        float w = W[i];
        __nv_bfloat16 h = __float2bfloat16(w);
        __nv_bfloat16 l = __float2bfloat16(w - __bfloat162float(h));
        H[(size_t)n * K + k] = h;
        L[(size_t)n * K + k] = l;
    }
}

// ---------------- aggregation: one warp per node, 4-way MLP -------------------
// dst[r] = dinv[r] * ( dinv[r]*src[r] + sum_{c in N(r)} dinv[c]*src[c] )
__global__ void k_gather(const int* __restrict__ offs, const int* __restrict__ col,
                         const float* __restrict__ dinv, const float4* __restrict__ src,
                         float4* __restrict__ dst) {
    int w    = (int)((blockIdx.x * (size_t)blockDim.x + threadIdx.x) >> 5);
    int lane = threadIdx.x & 31;
    if (w >= Nn) return;

    float di = __ldg(&dinv[w]);
    float4 s0 = __ldg(&src[(size_t)w * 32 + lane]);   // self term (weight di)
    s0.x *= di; s0.y *= di; s0.z *= di; s0.w *= di;
    float4 s1 = make_float4(0.f, 0.f, 0.f, 0.f);
    float4 s2 = make_float4(0.f, 0.f, 0.f, 0.f);
    float4 s3 = make_float4(0.f, 0.f, 0.f, 0.f);

    int beg = __ldg(&offs[w]), end = __ldg(&offs[w + 1]);
    int j = beg;
    for (; j + 4 <= end; j += 4) {
        int c0 = __ldg(&col[j]);
        int c1 = __ldg(&col[j + 1]);
        int c2 = __ldg(&col[j + 2]);
        int c3 = __ldg(&col[j + 3]);
        float w0 = __ldg(&dinv[c0]);
        float w1 = __ldg(&dinv[c1]);
        float w2 = __ldg(&dinv[c2]);
        float w3 = __ldg(&dinv[c3]);
        float4 v0 = __ldg(&src[(size_t)c0 * 32 + lane]);
        float4 v1 = __ldg(&src[(size_t)c1 * 32 + lane]);
        float4 v2 = __ldg(&src[(size_t)c2 * 32 + lane]);
        float4 v3 = __ldg(&src[(size_t)c3 * 32 + lane]);
        s0.x = fmaf(w0, v0.x, s0.x); s0.y = fmaf(w0, v0.y, s0.y);
        s0.z = fmaf(w0, v0.z, s0.z); s0.w = fmaf(w0, v0.w, s0.w);
        s1.x = fmaf(w1, v1.x, s1.x); s1.y = fmaf(w1, v1.y, s1.y);
        s1.z = fmaf(w1, v1.z, s1.z); s1.w = fmaf(w1, v1.w, s1.w);
        s2.x = fmaf(w2, v2.x, s2.x); s2.y = fmaf(w2, v2.y, s2.y);
        s2.z = fmaf(w2, v2.z, s2.z); s2.w = fmaf(w2, v2.w, s2.w);
        s3.x = fmaf(w3, v3.x, s3.x); s3.y = fmaf(w3, v3.y, s3.y);
        s3.z = fmaf(w3, v3.z, s3.z); s3.w = fmaf(w3, v3.w, s3.w);
    }
    for (; j < end; j++) {
        int c = __ldg(&col[j]);
        float wc = __ldg(&dinv[c]);
        float4 v = __ldg(&src[(size_t)c * 32 + lane]);
        s0.x = fmaf(wc, v.x, s0.x); s0.y = fmaf(wc, v.y, s0.y);
        s0.z = fmaf(wc, v.z, s0.z); s0.w = fmaf(wc, v.w, s0.w);
    }
    float4 o;
    o.x = di * (s0.x + s1.x + s2.x + s3.x);
    o.y = di * (s0.y + s1.y + s2.y + s3.y);
    o.z = di * (s0.z + s1.z + s2.z + s3.z);
    o.w = di * (s0.w + s1.w + s2.w + s3.w);
    dst[(size_t)w * 32 + lane] = o;
}

// ---------------- bf16 split-precision tensor-core GEMM (R5 proven) -----------
__device__ __forceinline__ void mma16816(float* c, const unsigned* a, unsigned b0, unsigned b1) {
    asm volatile(
        "mma.sync.aligned.m16n8k16.row.col.f32.bf16.bf16.f32 "
        "{%0,%1,%2,%3},{%4,%5,%6,%7},{%8,%9},{%0,%1,%2,%3};"
        : "+f"(c[0]), "+f"(c[1]), "+f"(c[2]), "+f"(c[3])
        : "r"(a[0]), "r"(a[1]), "r"(a[2]), "r"(a[3]), "r"(b0), "r"(b1));
}

template<int KEL, int NTILE, int NVALID, bool RELU>
__global__ void k_gemm_tc(const float* __restrict__ A, const __nv_bfloat16* __restrict__ WtH,
                          const __nv_bfloat16* __restrict__ WtL, const float* __restrict__ bias,
                          float* __restrict__ out, int nrows, int ldc) {
    constexpr int KSTR  = KEL + 8;
    constexpr int NT    = NTILE / 2;   // warp n-extent
    constexpr int NFRAG = NT / 8;
    extern __shared__ __nv_bfloat16 smb[];
    __nv_bfloat16* AsH = smb;
    __nv_bfloat16* AsL = AsH + 128 * KSTR;
    __nv_bfloat16* WsH = AsL + 128 * KSTR;
    __nv_bfloat16* WsL = WsH + NTILE * KSTR;

    int tid = threadIdx.x;
    int m0 = blockIdx.x * 128;
    int n0 = blockIdx.y * NTILE;

    // stage A: fp32 -> bf16 hi/lo
    constexpr int C4 = KEL / 4;
#pragma unroll
    for (int it = 0; it < 128 * C4 / 256; it++) {
        int i = tid + 256 * it;
        int r = i / C4, c4 = i % C4;
        float4 v = (m0 + r < nrows) ? ((const float4*)A)[(size_t)(m0 + r) * C4 + c4]
                                    : make_float4(0.f, 0.f, 0.f, 0.f);
        __nv_bfloat16 h0 = __float2bfloat16(v.x), h1 = __float2bfloat16(v.y);
        __nv_bfloat16 h2 = __float2bfloat16(v.z), h3 = __float2bfloat16(v.w);
        __nv_bfloat16 l0 = __float2bfloat16(v.x - __bfloat162float(h0));
        __nv_bfloat16 l1 = __float2bfloat16(v.y - __bfloat162float(h1));
        __nv_bfloat16 l2 = __float2bfloat16(v.z - __bfloat162float(h2));
        __nv_bfloat16 l3 = __float2bfloat16(v.w - __bfloat162float(h3));
        int o = r * KSTR + c4 * 4;
        *(__nv_bfloat162*)&AsH[o]     = __nv_bfloat162{h0, h1};
        *(__nv_bfloat162*)&AsH[o + 2] = __nv_bfloat162{h2, h3};
        *(__nv_bfloat162*)&AsL[o]     = __nv_bfloat162{l0, l1};
        *(__nv_bfloat162*)&AsL[o + 2] = __nv_bfloat162{l2, l3};
    }
    // stage Wt slice (rows n0..n0+NTILE-1), 16B chunks
    constexpr int C8 = KEL / 8;
    {
        const uint4* GH = (const uint4*)(WtH + (size_t)n0 * KEL);
        const uint4* GL = (const uint4*)(WtL + (size_t)n0 * KEL);
#pragma unroll
        for (int it = 0; it < NTILE * C8 / 256; it++) {
            int i = tid + 256 * it;
            int r = i / C8, c = i % C8;
            *(uint4*)((char*)WsH + r * (KSTR * 2) + c * 16) = GH[r * C8 + c];
            *(uint4*)((char*)WsL + r * (KSTR * 2) + c * 16) = GL[r * C8 + c];
        }
    }
    __syncthreads();

    int lane = tid & 31, wid = tid >> 5;
    int wm = (wid & 3) * 32;
    int wn = (wid >> 2) * NT;
    int g = lane >> 2, t = lane & 3;

    float acc[2][NFRAG][4];
#pragma unroll
    for (int mt = 0; mt < 2; mt++)
#pragma unroll
        for (int nt = 0; nt < NFRAG; nt++)
#pragma unroll
            for (int q = 0; q < 4; q++) acc[mt][nt][q] = 0.f;

#pragma unroll
    for (int ks = 0; ks < KEL / 16; ks++) {
        int k0 = ks * 16;
        unsigned aH[2][4], aL[2][4];
#pragma unroll
        for (int mt = 0; mt < 2; mt++) {
            int r = wm + mt * 16;
            aH[mt][0] = *(const unsigned*)&AsH[(r + g) * KSTR + k0 + 2 * t];
            aH[mt][1] = *(const unsigned*)&AsH[(r + g + 8) * KSTR + k0 + 2 * t];
            aH[mt][2] = *(const unsigned*)&AsH[(r + g) * KSTR + k0 + 8 + 2 * t];
            aH[mt][3] = *(const unsigned*)&AsH[(r + g + 8) * KSTR + k0 + 8 + 2 * t];
            aL[mt][0] = *(const unsigned*)&AsL[(r + g) * KSTR + k0 + 2 * t];
            aL[mt][1] = *(const unsigned*)&AsL[(r + g + 8) * KSTR + k0 + 2 * t];
            aL[mt][2] = *(const unsigned*)&AsL[(r + g) * KSTR + k0 + 8 + 2 * t];
            aL[mt][3] = *(const unsigned*)&AsL[(r + g + 8) * KSTR + k0 + 8 + 2 * t];
        }
#pragma unroll
        for (int nt = 0; nt < NFRAG; nt++) {
            int nn = wn + nt * 8 + g;
            unsigned bH0 = *(const unsigned*)&WsH[nn * KSTR + k0 + 2 * t];
            unsigned bH1 = *(const unsigned*)&WsH[nn * KSTR + k0 + 8 + 2 * t];
            unsigned bL0 = *(const unsigned*)&WsL[nn * KSTR + k0 + 2 * t];
            unsigned bL1 = *(const unsigned*)&WsL[nn * KSTR + k0 + 8 + 2 * t];
#pragma unroll
            for (int mt = 0; mt < 2; mt++) {
                mma16816(acc[mt][nt], aH[mt], bH0, bH1);
                mma16816(acc[mt][nt], aH[mt], bL0, bL1);
                mma16816(acc[mt][nt], aL[mt], bH0, bH1);
            }
        }
    }

    // epilogue
#pragma unroll
    for (int nt = 0; nt < NFRAG; nt++) {
        int cg = n0 + wn + nt * 8 + 2 * t;
        bool cok = cg < NVALID;        // NVALID even, cg even -> covers cg+1
        float bv0 = cok ? bias[cg] : 0.f;
        float bv1 = cok ? bias[cg + 1] : 0.f;
#pragma unroll
        for (int mt = 0; mt < 2; mt++) {
            int r0 = m0 + wm + mt * 16 + g;
            float v0 = acc[mt][nt][0] + bv0, v1 = acc[mt][nt][1] + bv1;
            float v2 = acc[mt][nt][2] + bv0, v3 = acc[mt][nt][3] + bv1;
            if (RELU) {
                v0 = fmaxf(v0, 0.f); v1 = fmaxf(v1, 0.f);
                v2 = fmaxf(v2, 0.f); v3 = fmaxf(v3, 0.f);
            }
            if (cok && r0 < nrows) {
                out[(size_t)r0 * ldc + cg]     = v0;
                out[(size_t)r0 * ldc + cg + 1] = v1;
            }
            if (cok && r0 + 8 < nrows) {
                out[(size_t)(r0 + 8) * ldc + cg]     = v2;
                out[(size_t)(r0 + 8) * ldc + cg + 1] = v3;
            }
        }
    }
}

#define SMEM_TC  (4 * 128 * 136 * 2)               // 139264 (KEL=128, NTILE=128)
#define SMEM_M2  ((2 * 128 + 2 * 64) * 264 * 2)    // 202752 (KEL=256, NTILE=64)

extern "C" void kernel_launch(void* const* d_in, const int* in_sizes, int n_in,
                              void* d_out, int out_size) {
    const float* x   = (const float*)d_in[0];
    const int*   ei  = (const int*)  d_in[1];
    const float* W0  = (const float*)d_in[2];
    const float* b0  = (const float*)d_in[3];
    const float* W1  = (const float*)d_in[4];
    const float* b1  = (const float*)d_in[5];
    const float* W2  = (const float*)d_in[6];
    const float* b2  = (const float*)d_in[7];
    const float* Wm1 = (const float*)d_in[8];
    const float* bm1 = (const float*)d_in[9];
    const float* Wm2 = (const float*)d_in[10];
    const float* bm2 = (const float*)d_in[11];
    float* out = (float*)d_out;

    const int n = Nn, e = Ee;

    int *degi, *offs, *col, *part, *base;
    float *dinv, *bufA, *bufB, *hid;
    __nv_bfloat16 *wtH, *wtL;
    cudaGetSymbolAddress((void**)&degi, g_degi);
    cudaGetSymbolAddress((void**)&offs, g_offs);
    cudaGetSymbolAddress((void**)&col,  g_col);
    cudaGetSymbolAddress((void**)&part, g_part);
    cudaGetSymbolAddress((void**)&base, g_base);
    cudaGetSymbolAddress((void**)&dinv, g_dinv);
    cudaGetSymbolAddress((void**)&bufA, g_bufA);
    cudaGetSymbolAddress((void**)&bufB, g_bufB);
    cudaGetSymbolAddress((void**)&hid,  g_hid);
    cudaGetSymbolAddress((void**)&wtH,  g_wtH);
    cudaGetSymbolAddress((void**)&wtL,  g_wtL);

    cudaFuncSetAttribute(k_gemm_tc<128, 128, 128, true>,
                         cudaFuncAttributeMaxDynamicSharedMemorySize, SMEM_TC);
    cudaFuncSetAttribute(k_gemm_tc<128, 128, 256, true>,
                         cudaFuncAttributeMaxDynamicSharedMemorySize, SMEM_TC);
    cudaFuncSetAttribute(k_gemm_tc<256, 64, 40, false>,
                         cudaFuncAttributeMaxDynamicSharedMemorySize, SMEM_M2);

    const int TB = 256;
    dim3 gN((n + TB - 1) / TB);
    dim3 gE((e + TB - 1) / TB);
    dim3 gNW(((size_t)n * 32 + TB - 1) / TB);
    dim3 gTC((n + 127) / 128, 1);
    dim3 gTC2((n + 127) / 128, 2);

    // ---- CSR build + normalization ----
    k_zero <<<gN, TB>>>(degi, n);
    k_count<<<gE, TB>>>(ei, degi, e);
    k_dinv <<<gN, TB>>>(degi, dinv, n);
    k_scanA<<<NB, 1024>>>(degi, part);
    k_scanB<<<1, 128>>>(part, base);
    k_scanC<<<NB, 1024>>>(degi, base, offs);
    k_fill <<<gE, TB>>>(ei, offs, degi, col, e);

    // ---- weight conversion (transposed bf16 hi/lo; Wm2 zero-padded to 64) ----
    k_bzero<<<(16384 + 255) / 256, 256>>>(wtH + WTM2, wtL + WTM2, 16384);
    k_wconv<<<(128 * 128 + 255) / 256, 256>>>(W0,  wtH + WT0,  wtL + WT0,  128, 128);
    k_wconv<<<(128 * 128 + 255) / 256, 256>>>(W1,  wtH + WT1,  wtL + WT1,  128, 128);
    k_wconv<<<(128 * 128 + 255) / 256, 256>>>(W2,  wtH + WT2,  wtL + WT2,  128, 128);
    k_wconv<<<(128 * 256 + 255) / 256, 256>>>(Wm1, wtH + WTM1, wtL + WTM1, 128, 256);
    k_wconv<<<(256 * 40 + 255) / 256, 256>>>(Wm2, wtH + WTM2, wtL + WTM2, 256, 40);

    // ---- layer 0 ----
    k_gather<<<gNW, TB>>>(offs, col, dinv, (const float4*)x, (float4*)bufA);
    k_gemm_tc<128, 128, 128, true><<<gTC, TB, SMEM_TC>>>(bufA, wtH + WT0, wtL + WT0, b0, bufB, n, 128);
    // ---- layer 1 ----
    k_gather<<<gNW, TB>>>(offs, col, dinv, (const float4*)bufB, (float4*)bufA);
    k_gemm_tc<128, 128, 128, true><<<gTC, TB, SMEM_TC>>>(bufA, wtH + WT1, wtL + WT1, b1, bufB, n, 128);
    // ---- layer 2 ----
    k_gather<<<gNW, TB>>>(offs, col, dinv, (const float4*)bufB, (float4*)bufA);
    k_gemm_tc<128, 128, 128, true><<<gTC, TB, SMEM_TC>>>(bufA, wtH + WT2, wtL + WT2, b2, bufB, n, 128);

    // ---- MLP ----
    k_gemm_tc<128, 128, 256, true><<<gTC2, TB, SMEM_TC>>>(bufB, wtH + WTM1, wtL + WTM1, bm1, hid, n, 256);
    k_gemm_tc<256, 64, 40, false><<<gTC, TB, SMEM_M2>>>(hid, wtH + WTM2, wtL + WTM2, bm2, out, n, 40);
}

// round 7
// speedup vs baseline: 1.1140x; 1.1140x over previous
#include <cuda_runtime.h>
#include <cuda_bf16.h>
#include <cuda_fp16.h>

#define Nn 100000
#define Ee 1600000
#define Dd 128
#define Hh 256
#define Ll 40
#define NB 98   // ceil(Nn / 1024)

// ---------------- scratch ------------------------------------------------------
__device__ int   g_degi[Nn];
__device__ int   g_offs[Nn + 1];
__device__ int   g_col[Ee];
__device__ int   g_part[NB];
__device__ int   g_base[NB];
__device__ float g_dinv[Nn];
__device__ float g_bufA[(size_t)Nn * Dd];     // gather output (fp32)
__device__ float g_bufB[(size_t)Nn * Dd];     // h3 (fp32)
__device__ float g_hid[(size_t)Nn * Hh];      // MLP hidden
__device__ __half g_xh[(size_t)Nn * Dd];      // fp16 x
__device__ __half g_actH[(size_t)Nn * Dd];    // fp16 h1 / h2
// transposed bf16 hi/lo weights [N][K]:
//   W0,W1,W2: 128x128 ; Wm1: 256x128 ; Wm2: 64(pad from 40)x256
#define WT0 0
#define WT1 16384
#define WT2 32768
#define WTM1 49152
#define WTM2 81920
__device__ __nv_bfloat16 g_wtH[98304];
__device__ __nv_bfloat16 g_wtL[98304];

// ---------------- CSR build ----------------------------------------------------
__global__ void k_zero(int* __restrict__ a, int n) {
    int i = blockIdx.x * blockDim.x + threadIdx.x;
    if (i < n) a[i] = 0;
}

__global__ void k_bzero(__nv_bfloat16* __restrict__ a, __nv_bfloat16* __restrict__ b, int n) {
    int i = blockIdx.x * blockDim.x + threadIdx.x;
    if (i < n) { a[i] = __float2bfloat16(0.f); b[i] = __float2bfloat16(0.f); }
}

__global__ void k_count(const int* __restrict__ ei, int* __restrict__ degi, int e) {
    int i = blockIdx.x * blockDim.x + threadIdx.x;
    if (i < e) atomicAdd(&degi[ei[i]], 1);
}

__global__ void k_dinv(const int* __restrict__ degi, float* __restrict__ dinv, int n) {
    int i = blockIdx.x * blockDim.x + threadIdx.x;
    if (i < n) dinv[i] = rsqrtf((float)degi[i] + 1.0f);
}

__global__ void k_scanA(const int* __restrict__ degi, int* __restrict__ part) {
    __shared__ int s[1024];
    int i = blockIdx.x * 1024 + threadIdx.x;
    s[threadIdx.x] = (i < Nn) ? degi[i] : 0;
    __syncthreads();
    for (int d = 512; d > 0; d >>= 1) {
        if (threadIdx.x < d) s[threadIdx.x] += s[threadIdx.x + d];
        __syncthreads();
    }
    if (threadIdx.x == 0) part[blockIdx.x] = s[0];
}

__global__ void k_scanB(const int* __restrict__ part, int* __restrict__ base) {
    __shared__ int s[128];
    int t = threadIdx.x;
    int v = (t < NB) ? part[t] : 0;
    s[t] = v;
    __syncthreads();
    for (int d = 1; d < 128; d <<= 1) {
        int u = (t >= d) ? s[t - d] : 0;
        __syncthreads();
        s[t] += u;
        __syncthreads();
    }
    if (t < NB) base[t] = s[t] - v;
}

__global__ void k_scanC(const int* __restrict__ degi, const int* __restrict__ base,
                        int* __restrict__ offs) {
    __shared__ int s[1024];
    int t = threadIdx.x;
    int i = blockIdx.x * 1024 + t;
    int v = (i < Nn) ? degi[i] : 0;
    s[t] = v;
    __syncthreads();
    for (int d = 1; d < 1024; d <<= 1) {
        int u = (t >= d) ? s[t - d] : 0;
        __syncthreads();
        s[t] += u;
        __syncthreads();
    }
    int exc = s[t] - v + base[blockIdx.x];
    if (i < Nn) {
        offs[i] = exc;
        if (i == Nn - 1) offs[Nn] = exc + v;
    }
}

__global__ void k_fill(const int* __restrict__ ei, const int* __restrict__ offs,
                       int* __restrict__ degi, int* __restrict__ col, int e) {
    int i = blockIdx.x * blockDim.x + threadIdx.x;
    if (i < e) {
        int r = ei[i];
        int c = ei[e + i];
        int pos = offs[r] + atomicSub(&degi[r], 1) - 1;
        col[pos] = c;
    }
}

// ---------------- weight conversion: W[K][N] -> Wt hi/lo [N][K] ---------------
__global__ void k_wconv(const float* __restrict__ W, __nv_bfloat16* __restrict__ H,
                        __nv_bfloat16* __restrict__ L, int K, int N) {
    int i = blockIdx.x * blockDim.x + threadIdx.x;
    if (i < K * N) {
        int k = i / N, n = i % N;
        float w = W[i];
        __nv_bfloat16 h = __float2bfloat16(w);
        __nv_bfloat16 l = __float2bfloat16(w - __bfloat162float(h));
        H[(size_t)n * K + k] = h;
        L[(size_t)n * K + k] = l;
    }
}

// ---------------- fp32 -> fp16 conversion (x once per launch) -----------------
__global__ void k_f2h(const float4* __restrict__ x, uint2* __restrict__ xh, int n4) {
    int t = blockIdx.x * blockDim.x + threadIdx.x;
    if (t < n4) {
        float4 v = x[t];
        __half2 a = __floats2half2_rn(v.x, v.y);
        __half2 b = __floats2half2_rn(v.z, v.w);
        uint2 u;
        u.x = *(unsigned*)&a;
        u.y = *(unsigned*)&b;
        xh[t] = u;
    }
}

// ---------------- aggregation: one warp per node, fp16 src, fp32 accum --------
// dst[r] = dinv[r] * ( dinv[r]*src[r] + sum_{c in N(r)} dinv[c]*src[c] )
__device__ __forceinline__ float4 h4_to_f4(uint2 u) {
    float2 f0 = __half22float2(*reinterpret_cast<__half2*>(&u.x));
    float2 f1 = __half22float2(*reinterpret_cast<__half2*>(&u.y));
    return make_float4(f0.x, f0.y, f1.x, f1.y);
}

__global__ void k_gather_h(const int* __restrict__ offs, const int* __restrict__ col,
                           const float* __restrict__ dinv, const uint2* __restrict__ src,
                           float4* __restrict__ dst) {
    int w    = (int)((blockIdx.x * (size_t)blockDim.x + threadIdx.x) >> 5);
    int lane = threadIdx.x & 31;
    if (w >= Nn) return;

    float di = __ldg(&dinv[w]);
    float4 acc = h4_to_f4(__ldg(&src[(size_t)w * 32 + lane]));
    acc.x *= di; acc.y *= di; acc.z *= di; acc.w *= di;

    int beg = __ldg(&offs[w]), end = __ldg(&offs[w + 1]);
    int c = (beg < end) ? __ldg(&col[beg]) : 0;
    for (int j = beg; j < end; j++) {
        int cn = (j + 1 < end) ? __ldg(&col[j + 1]) : 0;
        float wc = __ldg(&dinv[c]);
        float4 v = h4_to_f4(__ldg(&src[(size_t)c * 32 + lane]));
        acc.x = fmaf(wc, v.x, acc.x);
        acc.y = fmaf(wc, v.y, acc.y);
        acc.z = fmaf(wc, v.z, acc.z);
        acc.w = fmaf(wc, v.w, acc.w);
        c = cn;
    }
    acc.x *= di; acc.y *= di; acc.z *= di; acc.w *= di;
    dst[(size_t)w * 32 + lane] = acc;
}

// ---------------- bf16 split-precision tensor-core GEMM (R5 proven) -----------
__device__ __forceinline__ void mma16816(float* c, const unsigned* a, unsigned b0, unsigned b1) {
    asm volatile(
        "mma.sync.aligned.m16n8k16.row.col.f32.bf16.bf16.f32 "
        "{%0,%1,%2,%3},{%4,%5,%6,%7},{%8,%9},{%0,%1,%2,%3};"
        : "+f"(c[0]), "+f"(c[1]), "+f"(c[2]), "+f"(c[3])
        : "r"(a[0]), "r"(a[1]), "r"(a[2]), "r"(a[3]), "r"(b0), "r"(b1));
}

// OUTH: write fp16 output (for activations feeding the next gather)
template<int KEL, int NTILE, int NVALID, bool RELU, bool OUTH>
__global__ void k_gemm_tc(const float* __restrict__ A, const __nv_bfloat16* __restrict__ WtH,
                          const __nv_bfloat16* __restrict__ WtL, const float* __restrict__ bias,
                          void* __restrict__ outv, int nrows, int ldc) {
    constexpr int KSTR  = KEL + 8;
    constexpr int NT    = NTILE / 2;   // warp n-extent
    constexpr int NFRAG = NT / 8;
    extern __shared__ __nv_bfloat16 smb[];
    __nv_bfloat16* AsH = smb;
    __nv_bfloat16* AsL = AsH + 128 * KSTR;
    __nv_bfloat16* WsH = AsL + 128 * KSTR;
    __nv_bfloat16* WsL = WsH + NTILE * KSTR;

    int tid = threadIdx.x;
    int m0 = blockIdx.x * 128;
    int n0 = blockIdx.y * NTILE;

    // stage A: fp32 -> bf16 hi/lo
    constexpr int C4 = KEL / 4;
#pragma unroll
    for (int it = 0; it < 128 * C4 / 256; it++) {
        int i = tid + 256 * it;
        int r = i / C4, c4 = i % C4;
        float4 v = (m0 + r < nrows) ? ((const float4*)A)[(size_t)(m0 + r) * C4 + c4]
                                    : make_float4(0.f, 0.f, 0.f, 0.f);
        __nv_bfloat16 h0 = __float2bfloat16(v.x), h1 = __float2bfloat16(v.y);
        __nv_bfloat16 h2 = __float2bfloat16(v.z), h3 = __float2bfloat16(v.w);
        __nv_bfloat16 l0 = __float2bfloat16(v.x - __bfloat162float(h0));
        __nv_bfloat16 l1 = __float2bfloat16(v.y - __bfloat162float(h1));
        __nv_bfloat16 l2 = __float2bfloat16(v.z - __bfloat162float(h2));
        __nv_bfloat16 l3 = __float2bfloat16(v.w - __bfloat162float(h3));
        int o = r * KSTR + c4 * 4;
        *(__nv_bfloat162*)&AsH[o]     = __nv_bfloat162{h0, h1};
        *(__nv_bfloat162*)&AsH[o + 2] = __nv_bfloat162{h2, h3};
        *(__nv_bfloat162*)&AsL[o]     = __nv_bfloat162{l0, l1};
        *(__nv_bfloat162*)&AsL[o + 2] = __nv_bfloat162{l2, l3};
    }
    // stage Wt slice (rows n0..n0+NTILE-1), 16B chunks
    constexpr int C8 = KEL / 8;
    {
        const uint4* GH = (const uint4*)(WtH + (size_t)n0 * KEL);
        const uint4* GL = (const uint4*)(WtL + (size_t)n0 * KEL);
#pragma unroll
        for (int it = 0; it < NTILE * C8 / 256; it++) {
            int i = tid + 256 * it;
            int r = i / C8, c = i % C8;
            *(uint4*)((char*)WsH + r * (KSTR * 2) + c * 16) = GH[r * C8 + c];
            *(uint4*)((char*)WsL + r * (KSTR * 2) + c * 16) = GL[r * C8 + c];
        }
    }
    __syncthreads();

    int lane = tid & 31, wid = tid >> 5;
    int wm = (wid & 3) * 32;
    int wn = (wid >> 2) * NT;
    int g = lane >> 2, t = lane & 3;

    float acc[2][NFRAG][4];
#pragma unroll
    for (int mt = 0; mt < 2; mt++)
#pragma unroll
        for (int nt = 0; nt < NFRAG; nt++)
#pragma unroll
            for (int q = 0; q < 4; q++) acc[mt][nt][q] = 0.f;

#pragma unroll
    for (int ks = 0; ks < KEL / 16; ks++) {
        int k0 = ks * 16;
        unsigned aH[2][4], aL[2][4];
#pragma unroll
        for (int mt = 0; mt < 2; mt++) {
            int r = wm + mt * 16;
            aH[mt][0] = *(const unsigned*)&AsH[(r + g) * KSTR + k0 + 2 * t];
            aH[mt][1] = *(const unsigned*)&AsH[(r + g + 8) * KSTR + k0 + 2 * t];
            aH[mt][2] = *(const unsigned*)&AsH[(r + g) * KSTR + k0 + 8 + 2 * t];
            aH[mt][3] = *(const unsigned*)&AsH[(r + g + 8) * KSTR + k0 + 8 + 2 * t];
            aL[mt][0] = *(const unsigned*)&AsL[(r + g) * KSTR + k0 + 2 * t];
            aL[mt][1] = *(const unsigned*)&AsL[(r + g + 8) * KSTR + k0 + 2 * t];
            aL[mt][2] = *(const unsigned*)&AsL[(r + g) * KSTR + k0 + 8 + 2 * t];
            aL[mt][3] = *(const unsigned*)&AsL[(r + g + 8) * KSTR + k0 + 8 + 2 * t];
        }
#pragma unroll
        for (int nt = 0; nt < NFRAG; nt++) {
            int nn = wn + nt * 8 + g;
            unsigned bH0 = *(const unsigned*)&WsH[nn * KSTR + k0 + 2 * t];
            unsigned bH1 = *(const unsigned*)&WsH[nn * KSTR + k0 + 8 + 2 * t];
            unsigned bL0 = *(const unsigned*)&WsL[nn * KSTR + k0 + 2 * t];
            unsigned bL1 = *(const unsigned*)&WsL[nn * KSTR + k0 + 8 + 2 * t];
#pragma unroll
            for (int mt = 0; mt < 2; mt++) {
                mma16816(acc[mt][nt], aH[mt], bH0, bH1);
                mma16816(acc[mt][nt], aH[mt], bL0, bL1);
                mma16816(acc[mt][nt], aL[mt], bH0, bH1);
            }
        }
    }

    // epilogue
#pragma unroll
    for (int nt = 0; nt < NFRAG; nt++) {
        int cg = n0 + wn + nt * 8 + 2 * t;
        bool cok = cg < NVALID;        // NVALID even, cg even -> covers cg+1
        float bv0 = cok ? bias[cg] : 0.f;
        float bv1 = cok ? bias[cg + 1] : 0.f;
#pragma unroll
        for (int mt = 0; mt < 2; mt++) {
            int r0 = m0 + wm + mt * 16 + g;
            float v0 = acc[mt][nt][0] + bv0, v1 = acc[mt][nt][1] + bv1;
            float v2 = acc[mt][nt][2] + bv0, v3 = acc[mt][nt][3] + bv1;
            if (RELU) {
                v0 = fmaxf(v0, 0.f); v1 = fmaxf(v1, 0.f);
                v2 = fmaxf(v2, 0.f); v3 = fmaxf(v3, 0.f);
            }
            if (OUTH) {
                __half* oh = (__half*)outv;
                if (cok && r0 < nrows)
                    *(__half2*)&oh[(size_t)r0 * ldc + cg] = __floats2half2_rn(v0, v1);
                if (cok && r0 + 8 < nrows)
                    *(__half2*)&oh[(size_t)(r0 + 8) * ldc + cg] = __floats2half2_rn(v2, v3);
            } else {
                float* of = (float*)outv;
                if (cok && r0 < nrows) {
                    of[(size_t)r0 * ldc + cg]     = v0;
                    of[(size_t)r0 * ldc + cg + 1] = v1;
                }
                if (cok && r0 + 8 < nrows) {
                    of[(size_t)(r0 + 8) * ldc + cg]     = v2;
                    of[(size_t)(r0 + 8) * ldc + cg + 1] = v3;
                }
            }
        }
    }
}

#define SMEM_TC  (4 * 128 * 136 * 2)               // 139264 (KEL=128, NTILE=128)
#define SMEM_M2  ((2 * 128 + 2 * 64) * 264 * 2)    // 202752 (KEL=256, NTILE=64)

extern "C" void kernel_launch(void* const* d_in, const int* in_sizes, int n_in,
                              void* d_out, int out_size) {
    const float* x   = (const float*)d_in[0];
    const int*   ei  = (const int*)  d_in[1];
    const float* W0  = (const float*)d_in[2];
    const float* b0  = (const float*)d_in[3];
    const float* W1  = (const float*)d_in[4];
    const float* b1  = (const float*)d_in[5];
    const float* W2  = (const float*)d_in[6];
    const float* b2  = (const float*)d_in[7];
    const float* Wm1 = (const float*)d_in[8];
    const float* bm1 = (const float*)d_in[9];
    const float* Wm2 = (const float*)d_in[10];
    const float* bm2 = (const float*)d_in[11];
    float* out = (float*)d_out;

    const int n = Nn, e = Ee;

    int *degi, *offs, *col, *part, *base;
    float *dinv, *bufA, *bufB, *hid;
    __half *xh, *actH;
    __nv_bfloat16 *wtH, *wtL;
    cudaGetSymbolAddress((void**)&degi, g_degi);
    cudaGetSymbolAddress((void**)&offs, g_offs);
    cudaGetSymbolAddress((void**)&col,  g_col);
    cudaGetSymbolAddress((void**)&part, g_part);
    cudaGetSymbolAddress((void**)&base, g_base);
    cudaGetSymbolAddress((void**)&dinv, g_dinv);
    cudaGetSymbolAddress((void**)&bufA, g_bufA);
    cudaGetSymbolAddress((void**)&bufB, g_bufB);
    cudaGetSymbolAddress((void**)&hid,  g_hid);
    cudaGetSymbolAddress((void**)&xh,   g_xh);
    cudaGetSymbolAddress((void**)&actH, g_actH);
    cudaGetSymbolAddress((void**)&wtH,  g_wtH);
    cudaGetSymbolAddress((void**)&wtL,  g_wtL);

    cudaFuncSetAttribute(k_gemm_tc<128, 128, 128, true, true>,
                         cudaFuncAttributeMaxDynamicSharedMemorySize, SMEM_TC);
    cudaFuncSetAttribute(k_gemm_tc<128, 128, 128, true, false>,
                         cudaFuncAttributeMaxDynamicSharedMemorySize, SMEM_TC);
    cudaFuncSetAttribute(k_gemm_tc<128, 128, 256, true, false>,
                         cudaFuncAttributeMaxDynamicSharedMemorySize, SMEM_TC);
    cudaFuncSetAttribute(k_gemm_tc<256, 64, 40, false, false>,
                         cudaFuncAttributeMaxDynamicSharedMemorySize, SMEM_M2);

    const int TB = 256;
    dim3 gN((n + TB - 1) / TB);
    dim3 gE((e + TB - 1) / TB);
    dim3 gNW(((size_t)n * 32 + TB - 1) / TB);
    dim3 gF2H(((size_t)n * 32 + TB - 1) / TB);
    dim3 gTC((n + 127) / 128, 1);
    dim3 gTC2((n + 127) / 128, 2);

    // ---- CSR build + normalization ----
    k_zero <<<gN, TB>>>(degi, n);
    k_count<<<gE, TB>>>(ei, degi, e);
    k_dinv <<<gN, TB>>>(degi, dinv, n);
    k_scanA<<<NB, 1024>>>(degi, part);
    k_scanB<<<1, 128>>>(part, base);
    k_scanC<<<NB, 1024>>>(degi, base, offs);
    k_fill <<<gE, TB>>>(ei, offs, degi, col, e);

    // ---- weight conversion (transposed bf16 hi/lo; Wm2 zero-padded to 64) ----
    k_bzero<<<(16384 + 255) / 256, 256>>>(wtH + WTM2, wtL + WTM2, 16384);
    k_wconv<<<(128 * 128 + 255) / 256, 256>>>(W0,  wtH + WT0,  wtL + WT0,  128, 128);
    k_wconv<<<(128 * 128 + 255) / 256, 256>>>(W1,  wtH + WT1,  wtL + WT1,  128, 128);
    k_wconv<<<(128 * 128 + 255) / 256, 256>>>(W2,  wtH + WT2,  wtL + WT2,  128, 128);
    k_wconv<<<(128 * 256 + 255) / 256, 256>>>(Wm1, wtH + WTM1, wtL + WTM1, 128, 256);
    k_wconv<<<(256 * 40 + 255) / 256, 256>>>(Wm2, wtH + WTM2, wtL + WTM2, 256, 40);

    // ---- x -> fp16 ----
    k_f2h<<<gF2H, TB>>>((const float4*)x, (uint2*)xh, n * 32);

    // ---- layer 0: gather fp16 x, GEMM -> fp16 h1 ----
    k_gather_h<<<gNW, TB>>>(offs, col, dinv, (const uint2*)xh, (float4*)bufA);
    k_gemm_tc<128, 128, 128, true, true><<<gTC, TB, SMEM_TC>>>(
        bufA, wtH + WT0, wtL + WT0, b0, actH, n, 128);

    // ---- layer 1: gather fp16 h1, GEMM -> fp16 h2 ----
    k_gather_h<<<gNW, TB>>>(offs, col, dinv, (const uint2*)actH, (float4*)bufA);
    k_gemm_tc<128, 128, 128, true, true><<<gTC, TB, SMEM_TC>>>(
        bufA, wtH + WT1, wtL + WT1, b1, actH, n, 128);

    // ---- layer 2: gather fp16 h2, GEMM -> fp32 h3 ----
    k_gather_h<<<gNW, TB>>>(offs, col, dinv, (const uint2*)actH, (float4*)bufA);
    k_gemm_tc<128, 128, 128, true, false><<<gTC, TB, SMEM_TC>>>(
        bufA, wtH + WT2, wtL + WT2, b2, bufB, n, 128);

    // ---- MLP ----
    k_gemm_tc<128, 128, 256, true, false><<<gTC2, TB, SMEM_TC>>>(
        bufB, wtH + WTM1, wtL + WTM1, bm1, hid, n, 256);
    k_gemm_tc<256, 64, 40, false, false><<<gTC, TB, SMEM_M2>>>(
        hid, wtH + WTM2, wtL + WTM2, bm2, out, n, 40);
}